// round 4
// baseline (speedup 1.0000x reference)
#include <cuda_runtime.h>
#include <math.h>
#include <stdint.h>

// Problem constants
#define Bc   16
#define NHc  16
#define DIMc 512
#define Lc   2304          // 48*48
#define NWc  64            // (48/6)^2
#define HID  2048          // 4*DIM
#define SCALEc 0.17677669529663689f   // 32^-0.5
#define NTOK (Bc*Lc)       // 36864
#define NKVQ 1536          // fused kv(1024) + q(512)

// ---------------- scratch (device globals; no allocation allowed) ----------
__device__ float g_xn   [NTOK * DIMc];
__device__ float g_kvq  [NTOK * NKVQ];     // cols 0..511 k, 512..1023 v, 1024..1535 q
__device__ float g_x1   [NTOK * DIMc];
__device__ float g_h    [NTOK * HID];
__device__ float g_kvqavg[Bc * NKVQ];
__device__ float g_xavgn[Bc * DIMc];
__device__ float g_xavg1[Bc * DIMc];
__device__ float g_havg [Bc * HID];
// tf32-rounded / fused weights
__device__ float g_wkvq [DIMc * NKVQ];
__device__ float g_bkvq [NKVQ];
__device__ float g_wfc1r[DIMc * HID];
__device__ float g_wfc2r[HID * DIMc];

__device__ __forceinline__ float gelu_exact(float v) {
    return 0.5f * v * (1.0f + erff(v * 0.70710678118654752440f));
}

__device__ __forceinline__ float tf32r(float f) {
    uint32_t u;
    asm("cvt.rna.tf32.f32 %0, %1;" : "=r"(u) : "f"(f));
    return __uint_as_float(u);
}

#define CP16(dst, src) \
    asm volatile("cp.async.cg.shared.global [%0], [%1], 16;\n" :: "r"(dst), "l"(src))
#define CPCOMMIT() asm volatile("cp.async.commit_group;\n")

// ---------------- weight prep: fuse kv+q, round all weights to tf32 --------
__global__ __launch_bounds__(256)
void prep_weights(const float* __restrict__ w_kv, const float* __restrict__ b_kv,
                  const float* __restrict__ w_q,  const float* __restrict__ b_q,
                  const float* __restrict__ w_fc1, const float* __restrict__ w_fc2,
                  float* __restrict__ wkvq, float* __restrict__ bkvq,
                  float* __restrict__ wfc1r, float* __restrict__ wfc2r)
{
    const int stride = gridDim.x * blockDim.x;
    const int t0 = blockIdx.x * blockDim.x + threadIdx.x;
    for (int i = t0; i < DIMc * NKVQ; i += stride) {
        const int k = i / NKVQ, j = i % NKVQ;
        const float v = (j < 2 * DIMc) ? w_kv[k * (2 * DIMc) + j]
                                       : w_q [k * DIMc + (j - 2 * DIMc)];
        wkvq[i] = tf32r(v);
    }
    for (int i = t0; i < DIMc * HID; i += stride) wfc1r[i] = tf32r(w_fc1[i]);
    for (int i = t0; i < HID * DIMc; i += stride) wfc2r[i] = tf32r(w_fc2[i]);
    if (t0 < NKVQ) bkvq[t0] = (t0 < 2 * DIMc) ? b_kv[t0] : b_q[t0 - 2 * DIMc];
}

// ---------------- LayerNorm over DIM=512, one block per token --------------
// ROUND: emit tf32-rounded output (feeds tensor-core GEMMs)
template<bool ROUND>
__global__ __launch_bounds__(128)
void ln_kernel(const float* __restrict__ x, const float* __restrict__ g,
               const float* __restrict__ be, float* __restrict__ y)
{
    __shared__ float sS[4], sQ[4];
    const int t = blockIdx.x;
    const int tid = threadIdx.x;
    const float4 v = ((const float4*)(x + (size_t)t * DIMc))[tid];
    float s = v.x + v.y + v.z + v.w;
    float q = v.x*v.x + v.y*v.y + v.z*v.z + v.w*v.w;
    #pragma unroll
    for (int o = 16; o; o >>= 1) {
        s += __shfl_xor_sync(0xffffffffu, s, o);
        q += __shfl_xor_sync(0xffffffffu, q, o);
    }
    if ((tid & 31) == 0) { sS[tid >> 5] = s; sQ[tid >> 5] = q; }
    __syncthreads();
    const float S = sS[0] + sS[1] + sS[2] + sS[3];
    const float Q = sQ[0] + sQ[1] + sQ[2] + sQ[3];
    const float mean = S * (1.0f / 512.0f);
    const float var  = Q * (1.0f / 512.0f) - mean * mean;
    const float rstd = rsqrtf(var + 1e-3f);
    const float4 gg = ((const float4*)g)[tid];
    const float4 bb = ((const float4*)be)[tid];
    float4 o;
    o.x = (v.x - mean) * rstd * gg.x + bb.x;
    o.y = (v.y - mean) * rstd * gg.y + bb.y;
    o.z = (v.z - mean) * rstd * gg.z + bb.z;
    o.w = (v.w - mean) * rstd * gg.w + bb.w;
    if (ROUND) { o.x = tf32r(o.x); o.y = tf32r(o.y); o.z = tf32r(o.z); o.w = tf32r(o.w); }
    ((float4*)(y + (size_t)t * DIMc))[tid] = o;
}

// ---------------- tf32 tensor-core GEMM (pre-rounded operands) -------------
// C[MxN] = act(A @ W + bias)(+R). 128x128x32 tile, 256 threads, 2x4 warps
// (64x32 per warp), mma.m16n8k8.tf32, double-buffered cp.async, no cvt in
// the mainloop (operands already tf32-rounded).
template<int ACT, bool RES, bool ROUND>
__global__ __launch_bounds__(256, 2)
void tgemm(int M, int N, int K,
           const float* __restrict__ A, const float* __restrict__ W,
           const float* __restrict__ bias, const float* __restrict__ R,
           float* __restrict__ C)
{
    constexpr int BM = 128, BN = 128, BK = 32;
    constexpr int APAD = 36;   // floats per A row (bank-conflict-free)
    constexpr int BPAD = 136;  // floats per B row

    __shared__ float As[2][BM * APAD];
    __shared__ float Bs[2][BK * BPAD];

    const int tid  = threadIdx.x;
    const int lane = tid & 31;
    const int warp = tid >> 5;
    const int wm   = warp >> 2;          // 0..1
    const int wn   = warp & 3;           // 0..3
    const int bm   = blockIdx.y * BM;
    const int bn   = blockIdx.x * BN;

    // A: 128 rows x 32 floats; thread t: row=t>>1, half=(t&1)*16, 4x16B chunks
    const int a_r = tid >> 1;
    const int a_c = (tid & 1) << 4;
    const float* a_src = A + (size_t)(bm + a_r) * K + a_c;
    // B: 32 rows x 128 floats; thread t: row=t>>3, 4x16B chunks at (t&7)*16
    const int b_r = tid >> 3;
    const int b_c = (tid & 7) << 4;
    const float* b_src = W + (size_t)b_r * N + bn + b_c;

    const uint32_t sA0 = (uint32_t)__cvta_generic_to_shared(&As[0][0]);
    const uint32_t sB0 = (uint32_t)__cvta_generic_to_shared(&Bs[0][0]);
    const uint32_t a_dst = sA0 + (uint32_t)(a_r * APAD + a_c) * 4u;
    const uint32_t b_dst = sB0 + (uint32_t)(b_r * BPAD + b_c) * 4u;
    const uint32_t aBuf = (uint32_t)(BM * APAD) * 4u;
    const uint32_t bBuf = (uint32_t)(BK * BPAD) * 4u;

    float acc[4][4][4] = {};
    const int T = K / BK;

    // prologue: stage tile 0 into buf 0
    #pragma unroll
    for (int i = 0; i < 4; i++) CP16(a_dst + 16u * i, a_src + 4 * i);
    #pragma unroll
    for (int i = 0; i < 4; i++) CP16(b_dst + 16u * i, b_src + 4 * i);
    CPCOMMIT();

    const int ar = wm * 64 + (lane >> 2);
    const int ac = lane & 3;
    const int bc = wn * 32 + (lane >> 2);
    const int br = lane & 3;

    int buf = 0;
    for (int t = 0; t < T; t++) {
        asm volatile("cp.async.wait_group 0;\n");
        __syncthreads();

        if (t + 1 < T) {
            const int k0 = (t + 1) * BK;
            const uint32_t ao = (buf ^ 1) * aBuf;
            const uint32_t bo = (buf ^ 1) * bBuf;
            #pragma unroll
            for (int i = 0; i < 4; i++) CP16(a_dst + ao + 16u * i, a_src + k0 + 4 * i);
            #pragma unroll
            for (int i = 0; i < 4; i++) CP16(b_dst + bo + 16u * i, b_src + (size_t)k0 * N + 4 * i);
            CPCOMMIT();
        }

        const uint32_t* As32 = (const uint32_t*)&As[buf][0];
        const uint32_t* Bs32 = (const uint32_t*)&Bs[buf][0];

        #pragma unroll
        for (int ks = 0; ks < BK; ks += 8) {
            uint32_t af[4][4];
            #pragma unroll
            for (int mt = 0; mt < 4; mt++) {
                const uint32_t* p = As32 + (ar + mt * 16) * APAD + ks + ac;
                af[mt][0] = p[0];
                af[mt][1] = p[8 * APAD];
                af[mt][2] = p[4];
                af[mt][3] = p[8 * APAD + 4];
            }
            uint32_t bf[4][2];
            #pragma unroll
            for (int nt = 0; nt < 4; nt++) {
                const uint32_t* p = Bs32 + (ks + br) * BPAD + bc + nt * 8;
                bf[nt][0] = p[0];
                bf[nt][1] = p[4 * BPAD];
            }
            #pragma unroll
            for (int mt = 0; mt < 4; mt++)
                #pragma unroll
                for (int nt = 0; nt < 4; nt++)
                    asm volatile(
                        "mma.sync.aligned.m16n8k8.row.col.f32.tf32.tf32.f32 "
                        "{%0,%1,%2,%3}, {%4,%5,%6,%7}, {%8,%9}, {%0,%1,%2,%3};\n"
                        : "+f"(acc[mt][nt][0]), "+f"(acc[mt][nt][1]),
                          "+f"(acc[mt][nt][2]), "+f"(acc[mt][nt][3])
                        : "r"(af[mt][0]), "r"(af[mt][1]), "r"(af[mt][2]), "r"(af[mt][3]),
                          "r"(bf[nt][0]), "r"(bf[nt][1]));
        }
        buf ^= 1;
    }

    // ---- epilogue ----
    #pragma unroll
    for (int mt = 0; mt < 4; mt++) {
        #pragma unroll
        for (int nt = 0; nt < 4; nt++) {
            const int r0 = bm + wm * 64 + mt * 16 + (lane >> 2);
            const int c  = bn + wn * 32 + nt * 8 + (lane & 3) * 2;
            const float bx = bias[c], by = bias[c + 1];
            #pragma unroll
            for (int half = 0; half < 2; half++) {
                const int r = r0 + half * 8;
                float vx = acc[mt][nt][half * 2 + 0] + bx;
                float vy = acc[mt][nt][half * 2 + 1] + by;
                if (ACT == 1) { vx = gelu_exact(vx); vy = gelu_exact(vy); }
                if (ROUND) { vx = tf32r(vx); vy = tf32r(vy); }
                if (RES) {
                    const float2 rr = *(const float2*)(R + (size_t)r * N + c);
                    vx += rr.x; vy += rr.y;
                }
                float2 o; o.x = vx; o.y = vy;
                *(float2*)(C + (size_t)r * N + c) = o;
            }
        }
    }
}

// ---------------- tiny GEMM for the 16 global tokens -----------------------
template<int ACT, bool RES>
__global__ __launch_bounds__(128)
void small_gemm(int N, int K,
                const float* __restrict__ A, const float* __restrict__ W,
                const float* __restrict__ bias, const float* __restrict__ R,
                float* __restrict__ C)
{
    const int r = blockIdx.y;
    const int n = blockIdx.x * 128 + threadIdx.x;
    const float* a = A + (size_t)r * K;
    float acc = 0.0f;
    #pragma unroll 8
    for (int k = 0; k < K; k++)
        acc = fmaf(__ldg(a + k), W[(size_t)k * N + n], acc);
    float v = acc + bias[n];
    if (ACT == 1) v = gelu_exact(v);
    if (RES) v += R[(size_t)r * N + n];
    C[(size_t)r * N + n] = v;
}

// ---------------- window attention: one block per (window, head) -----------
// kvq rows have stride 1536: [k(512) | v(512) | q(512)]
__global__ __launch_bounds__(128)
void win_attn(const float* __restrict__ kvq, const float* __restrict__ kvqavg,
              const float* __restrict__ table,
              const float* __restrict__ xin, float* __restrict__ x1)
{
    const int w = blockIdx.x;            // 0..1023
    const int h = blockIdx.y;            // 0..15
    const int b  = w >> 6;
    const int wi = w & 63;
    const int wr = wi >> 3, wc = wi & 7;

    __shared__ float qs[36][33];
    __shared__ float ks[37][33];
    __shared__ float vs[37][33];
    __shared__ float sc[36][37];

    const int tid = threadIdx.x;

    for (int idx = tid; idx < 36 * 32; idx += 128) {
        const int m = idx >> 5, d = idx & 31;
        const int r = m / 6, c = m % 6;
        const int l = (wr * 6 + r) * 48 + wc * 6 + c;
        const float* row = kvq + (size_t)(b * Lc + l) * NKVQ + h * 32 + d;
        ks[m][d] = row[0];
        vs[m][d] = row[DIMc];
        qs[m][d] = row[2 * DIMc] * SCALEc;
    }
    if (tid < 32) {
        const float* row = kvqavg + (size_t)b * NKVQ + h * 32 + tid;
        ks[36][tid] = row[0];
        vs[36][tid] = row[DIMc];
    }
    __syncthreads();

    for (int p = tid; p < 36 * 37; p += 128) {
        const int mq = p / 37, mk = p % 37;
        float acc = 0.0f;
        #pragma unroll
        for (int d = 0; d < 32; d++) acc = fmaf(qs[mq][d], ks[mk][d], acc);
        int d0, d1;
        if (mk == 36) { d0 = mq % 6; d1 = mq / 6; }
        else          { d0 = mq % 6 - mk % 6; d1 = mq / 6 - mk / 6; }
        const int idx = (d0 + 5) * 11 + (d1 + 5);
        sc[mq][mk] = acc + table[idx * NHc + h];
    }
    __syncthreads();

    if (tid < 36) {
        float mx = -1e30f;
        #pragma unroll
        for (int k = 0; k < 37; k++) mx = fmaxf(mx, sc[tid][k]);
        float sum = 0.0f;
        #pragma unroll
        for (int k = 0; k < 37; k++) { const float e = expf(sc[tid][k] - mx); sc[tid][k] = e; sum += e; }
        const float inv = 1.0f / sum;
        #pragma unroll
        for (int k = 0; k < 37; k++) sc[tid][k] *= inv;
    }
    __syncthreads();

    for (int idx = tid; idx < 36 * 32; idx += 128) {
        const int m = idx >> 5, d = idx & 31;
        float acc = 0.0f;
        #pragma unroll
        for (int k = 0; k < 37; k++) acc = fmaf(sc[m][k], vs[k][d], acc);
        const int r = m / 6, c = m % 6;
        const int l = (wr * 6 + r) * 48 + wc * 6 + c;
        const size_t o = (size_t)(b * Lc + l) * DIMc + h * 32 + d;
        x1[o] = xin[o] + acc;
    }
}

// ---------------- global-token attention: one block per (b, h) -------------
__global__ __launch_bounds__(256)
void glob_attn(const float* __restrict__ kvqavg, const float* __restrict__ kvq,
               const float* __restrict__ xavg_in, float* __restrict__ xavg1)
{
    const int b = blockIdx.x, h = blockIdx.y;
    __shared__ float qsh[32];
    __shared__ float wgt[Lc];
    __shared__ float red[8];
    const int tid = threadIdx.x, lane = tid & 31, wn = tid >> 5;

    if (tid < 32) qsh[tid] = kvqavg[(size_t)b * NKVQ + 2 * DIMc + h * 32 + tid] * SCALEc;
    __syncthreads();

    float lmax = -1e30f;
    for (int k = tid; k < Lc; k += 256) {
        const float4* kp = (const float4*)(kvq + (size_t)(b * Lc + k) * NKVQ + h * 32);
        float acc = 0.0f;
        #pragma unroll
        for (int d4 = 0; d4 < 8; d4++) {
            const float4 kk = kp[d4];
            acc = fmaf(qsh[d4*4+0], kk.x, acc);
            acc = fmaf(qsh[d4*4+1], kk.y, acc);
            acc = fmaf(qsh[d4*4+2], kk.z, acc);
            acc = fmaf(qsh[d4*4+3], kk.w, acc);
        }
        wgt[k] = acc;
        lmax = fmaxf(lmax, acc);
    }
    #pragma unroll
    for (int o = 16; o; o >>= 1) lmax = fmaxf(lmax, __shfl_xor_sync(0xffffffffu, lmax, o));
    if (lane == 0) red[wn] = lmax;
    __syncthreads();
    float gmax = red[0];
    #pragma unroll
    for (int i = 1; i < 8; i++) gmax = fmaxf(gmax, red[i]);
    __syncthreads();

    float lsum = 0.0f;
    for (int k = tid; k < Lc; k += 256) {
        const float e = expf(wgt[k] - gmax);
        wgt[k] = e;
        lsum += e;
    }
    #pragma unroll
    for (int o = 16; o; o >>= 1) lsum += __shfl_xor_sync(0xffffffffu, lsum, o);
    if (lane == 0) red[wn] = lsum;
    __syncthreads();
    float gsum = 0.0f;
    #pragma unroll
    for (int i = 0; i < 8; i++) gsum += red[i];
    const float inv = 1.0f / gsum;

    float acc[4] = {0.f, 0.f, 0.f, 0.f};
    for (int k = lane; k < Lc; k += 32) {
        const float wk = wgt[k];
        const float4 vv = *(const float4*)(kvq + (size_t)(b * Lc + k) * NKVQ + DIMc + h * 32 + wn * 4);
        acc[0] = fmaf(wk, vv.x, acc[0]);
        acc[1] = fmaf(wk, vv.y, acc[1]);
        acc[2] = fmaf(wk, vv.z, acc[2]);
        acc[3] = fmaf(wk, vv.w, acc[3]);
    }
    #pragma unroll
    for (int j = 0; j < 4; j++) {
        #pragma unroll
        for (int o = 16; o; o >>= 1) acc[j] += __shfl_xor_sync(0xffffffffu, acc[j], o);
    }
    if (lane == 0) {
        #pragma unroll
        for (int j = 0; j < 4; j++) {
            const size_t o = (size_t)b * DIMc + h * 32 + wn * 4 + j;
            xavg1[o] = xavg_in[o] + acc[j] * inv;
        }
    }
}

// ---------------------------------------------------------------------------
extern "C" void kernel_launch(void* const* d_in, const int* in_sizes, int n_in,
                              void* d_out, int out_size)
{
    const float* x     = (const float*)d_in[0];
    const float* xavg  = (const float*)d_in[1];
    const float* w_kv  = (const float*)d_in[2];
    const float* b_kv  = (const float*)d_in[3];
    const float* w_q   = (const float*)d_in[4];
    const float* b_q   = (const float*)d_in[5];
    const float* table = (const float*)d_in[6];
    const float* g1    = (const float*)d_in[7];
    const float* be1   = (const float*)d_in[8];
    const float* g2    = (const float*)d_in[9];
    const float* be2   = (const float*)d_in[10];
    const float* w_fc1 = (const float*)d_in[11];
    const float* b_fc1 = (const float*)d_in[12];
    const float* w_fc2 = (const float*)d_in[13];
    const float* b_fc2 = (const float*)d_in[14];
    float* out = (float*)d_out;

    float *xn, *kvq, *x1, *hbuf, *kvqavg, *xavgn, *xavg1, *havg;
    float *wkvq, *bkvq, *wfc1r, *wfc2r;
    cudaGetSymbolAddress((void**)&xn,     g_xn);
    cudaGetSymbolAddress((void**)&kvq,    g_kvq);
    cudaGetSymbolAddress((void**)&x1,     g_x1);
    cudaGetSymbolAddress((void**)&hbuf,   g_h);
    cudaGetSymbolAddress((void**)&kvqavg, g_kvqavg);
    cudaGetSymbolAddress((void**)&xavgn,  g_xavgn);
    cudaGetSymbolAddress((void**)&xavg1,  g_xavg1);
    cudaGetSymbolAddress((void**)&havg,   g_havg);
    cudaGetSymbolAddress((void**)&wkvq,   g_wkvq);
    cudaGetSymbolAddress((void**)&bkvq,   g_bkvq);
    cudaGetSymbolAddress((void**)&wfc1r,  g_wfc1r);
    cudaGetSymbolAddress((void**)&wfc2r,  g_wfc2r);

    // 0. fuse + tf32-round weights
    prep_weights<<<592, 256>>>(w_kv, b_kv, w_q, b_q, w_fc1, w_fc2,
                               wkvq, bkvq, wfc1r, wfc2r);

    // 1. LayerNorm 1 (tf32-rounded outputs feed GEMMs)
    ln_kernel<true><<<NTOK, 128>>>(x,    g1, be1, xn);
    ln_kernel<true><<<Bc,   128>>>(xavg, g1, be1, xavgn);

    // 2. Fused kvq projection (one GEMM for k|v|q)
    tgemm<0, false, false><<<dim3(NKVQ/128, NTOK/128), 256>>>(NTOK, NKVQ, DIMc, xn, wkvq, bkvq, nullptr, kvq);
    small_gemm<0, false><<<dim3(NKVQ/128, Bc), 128>>>(NKVQ, DIMc, xavgn, wkvq, bkvq, nullptr, kvqavg);

    // 3. Attention (+ residual)
    win_attn <<<dim3(Bc*NWc, NHc), 128>>>(kvq, kvqavg, table, x, x1);
    glob_attn<<<dim3(Bc,     NHc), 256>>>(kvqavg, kvq, xavg, xavg1);

    // 4. LayerNorm 2
    ln_kernel<true><<<NTOK, 128>>>(x1,    g2, be2, xn);
    ln_kernel<true><<<Bc,   128>>>(xavg1, g2, be2, xavgn);

    // 5. MLP (+ residual), final outputs
    tgemm<1, false, true ><<<dim3(HID/128,  NTOK/128), 256>>>(NTOK, HID,  DIMc, xn,   wfc1r, b_fc1, nullptr, hbuf);
    tgemm<0, true,  false><<<dim3(DIMc/128, NTOK/128), 256>>>(NTOK, DIMc, HID,  hbuf, wfc2r, b_fc2, x1, out);
    small_gemm<1, false><<<dim3(HID/128,  Bc), 128>>>(HID,  DIMc, xavgn, wfc1r, b_fc1, nullptr, havg);
    small_gemm<0, true ><<<dim3(DIMc/128, Bc), 128>>>(DIMc, HID,  havg,  wfc2r, b_fc2, xavg1, out + (size_t)NTOK * DIMc);
}

// round 5
// speedup vs baseline: 1.1467x; 1.1467x over previous
#include <cuda_runtime.h>
#include <math.h>
#include <stdint.h>

// Problem constants
#define Bc   16
#define NHc  16
#define DIMc 512
#define Lc   2304          // 48*48
#define NWc  64            // (48/6)^2
#define HID  2048          // 4*DIM
#define SCALEc 0.17677669529663689f   // 32^-0.5
#define NTOK (Bc*Lc)       // 36864
#define NKVQ 1536          // fused kv(1024) + q(512)

// ---------------- scratch (device globals; no allocation allowed) ----------
__device__ float g_xn   [NTOK * DIMc];
__device__ float g_kvq  [NTOK * NKVQ];     // cols 0..511 k, 512..1023 v, 1024..1535 q
__device__ float g_x1   [NTOK * DIMc];
__device__ float g_h    [NTOK * HID];
__device__ float g_kvqavg[Bc * NKVQ];
__device__ float g_xavgn[Bc * DIMc];
__device__ float g_xavg1[Bc * DIMc];
__device__ float g_havg [Bc * HID];
// tf32-rounded / fused weights
__device__ float g_wkvq [DIMc * NKVQ];
__device__ float g_bkvq [NKVQ];
__device__ float g_wfc1r[DIMc * HID];
__device__ float g_wfc2r[HID * DIMc];

__device__ __forceinline__ float gelu_exact(float v) {
    return 0.5f * v * (1.0f + erff(v * 0.70710678118654752440f));
}

__device__ __forceinline__ float tf32r(float f) {
    uint32_t u;
    asm("cvt.rna.tf32.f32 %0, %1;" : "=r"(u) : "f"(f));
    return __uint_as_float(u);
}

#define CP16(dst, src) \
    asm volatile("cp.async.cg.shared.global [%0], [%1], 16;\n" :: "r"(dst), "l"(src))
#define CPCOMMIT() asm volatile("cp.async.commit_group;\n")

// ---------------- weight prep: fuse kv+q, round all weights to tf32 --------
__global__ __launch_bounds__(256)
void prep_weights(const float* __restrict__ w_kv, const float* __restrict__ b_kv,
                  const float* __restrict__ w_q,  const float* __restrict__ b_q,
                  const float* __restrict__ w_fc1, const float* __restrict__ w_fc2,
                  float* __restrict__ wkvq, float* __restrict__ bkvq,
                  float* __restrict__ wfc1r, float* __restrict__ wfc2r)
{
    const int stride = gridDim.x * blockDim.x;
    const int t0 = blockIdx.x * blockDim.x + threadIdx.x;
    for (int i = t0; i < DIMc * NKVQ; i += stride) {
        const int k = i / NKVQ, j = i % NKVQ;
        const float v = (j < 2 * DIMc) ? w_kv[k * (2 * DIMc) + j]
                                       : w_q [k * DIMc + (j - 2 * DIMc)];
        wkvq[i] = tf32r(v);
    }
    for (int i = t0; i < DIMc * HID; i += stride) wfc1r[i] = tf32r(w_fc1[i]);
    for (int i = t0; i < HID * DIMc; i += stride) wfc2r[i] = tf32r(w_fc2[i]);
    if (t0 < NKVQ) bkvq[t0] = (t0 < 2 * DIMc) ? b_kv[t0] : b_q[t0 - 2 * DIMc];
}

// ---------------- LayerNorm over DIM=512, one block per token --------------
template<bool ROUND>
__global__ __launch_bounds__(128)
void ln_kernel(const float* __restrict__ x, const float* __restrict__ g,
               const float* __restrict__ be, float* __restrict__ y)
{
    __shared__ float sS[4], sQ[4];
    const int t = blockIdx.x;
    const int tid = threadIdx.x;
    const float4 v = ((const float4*)(x + (size_t)t * DIMc))[tid];
    float s = v.x + v.y + v.z + v.w;
    float q = v.x*v.x + v.y*v.y + v.z*v.z + v.w*v.w;
    #pragma unroll
    for (int o = 16; o; o >>= 1) {
        s += __shfl_xor_sync(0xffffffffu, s, o);
        q += __shfl_xor_sync(0xffffffffu, q, o);
    }
    if ((tid & 31) == 0) { sS[tid >> 5] = s; sQ[tid >> 5] = q; }
    __syncthreads();
    const float S = sS[0] + sS[1] + sS[2] + sS[3];
    const float Q = sQ[0] + sQ[1] + sQ[2] + sQ[3];
    const float mean = S * (1.0f / 512.0f);
    const float var  = Q * (1.0f / 512.0f) - mean * mean;
    const float rstd = rsqrtf(var + 1e-3f);
    const float4 gg = ((const float4*)g)[tid];
    const float4 bb = ((const float4*)be)[tid];
    float4 o;
    o.x = (v.x - mean) * rstd * gg.x + bb.x;
    o.y = (v.y - mean) * rstd * gg.y + bb.y;
    o.z = (v.z - mean) * rstd * gg.z + bb.z;
    o.w = (v.w - mean) * rstd * gg.w + bb.w;
    if (ROUND) { o.x = tf32r(o.x); o.y = tf32r(o.y); o.z = tf32r(o.z); o.w = tf32r(o.w); }
    ((float4*)(y + (size_t)t * DIMc))[tid] = o;
}

// ---------------- tf32 tensor-core GEMM (pre-rounded, 3-stage pipe) --------
// C[MxN] = act(A @ W + bias)(+R). 128x128x16 tile, 256 threads, 2x4 warps
// (64x32 per warp), mma.m16n8k8.tf32, 3-stage cp.async pipeline.
template<int ACT, bool RES, bool ROUND>
__global__ __launch_bounds__(256, 2)
void tgemm(int M, int N, int K,
           const float* __restrict__ A, const float* __restrict__ W,
           const float* __restrict__ bias, const float* __restrict__ R,
           float* __restrict__ C)
{
    constexpr int BM = 128, BN = 128, BK = 16;
    constexpr int APAD = 20;   // floats per A row
    constexpr int BPAD = 132;  // floats per B row
    constexpr int STG = 3;

    __shared__ float As[STG][BM * APAD];
    __shared__ float Bs[STG][BK * BPAD];

    const int tid  = threadIdx.x;
    const int lane = tid & 31;
    const int warp = tid >> 5;
    const int wm   = warp >> 2;          // 0..1
    const int wn   = warp & 3;           // 0..3
    const int bm   = blockIdx.y * BM;
    const int bn   = blockIdx.x * BN;

    // A tile: 128 rows x 16 floats = 512 x 16B chunks; 2 per thread
    const int a_r = tid >> 2;                 // 0..63
    const int a_p = (tid & 3) << 2;           // 0,4,8,12
    const float* a_src0 = A + (size_t)(bm + a_r) * K + a_p;
    const float* a_src1 = a_src0 + (size_t)64 * K;
    // B tile: 16 rows x 128 floats = 512 x 16B chunks; 2 per thread
    const int b_r = tid >> 5;                 // 0..7
    const int b_c = lane << 2;                // 0..124
    const float* b_src0 = W + (size_t)b_r * N + bn + b_c;
    const float* b_src1 = b_src0 + (size_t)8 * N;

    const uint32_t sA0 = (uint32_t)__cvta_generic_to_shared(&As[0][0]);
    const uint32_t sB0 = (uint32_t)__cvta_generic_to_shared(&Bs[0][0]);
    const uint32_t a_dst0 = sA0 + (uint32_t)(a_r * APAD + a_p) * 4u;
    const uint32_t a_dst1 = a_dst0 + (uint32_t)(64 * APAD) * 4u;
    const uint32_t b_dst0 = sB0 + (uint32_t)(b_r * BPAD + b_c) * 4u;
    const uint32_t b_dst1 = b_dst0 + (uint32_t)(8 * BPAD) * 4u;
    const uint32_t aBuf = (uint32_t)(BM * APAD) * 4u;
    const uint32_t bBuf = (uint32_t)(BK * BPAD) * 4u;

    float acc[4][4][4] = {};
    const int T = K / BK;

    // prologue: stage 0 and stage 1
    {
        CP16(a_dst0, a_src0); CP16(a_dst1, a_src1);
        CP16(b_dst0, b_src0); CP16(b_dst1, b_src1);
        CPCOMMIT();
        const uint32_t ao = aBuf, bo = bBuf;
        CP16(a_dst0 + ao, a_src0 + BK); CP16(a_dst1 + ao, a_src1 + BK);
        CP16(b_dst0 + bo, b_src0 + (size_t)BK * N); CP16(b_dst1 + bo, b_src1 + (size_t)BK * N);
        CPCOMMIT();
    }

    const int ar = wm * 64 + (lane >> 2);
    const int ac = lane & 3;
    const int bc = wn * 32 + (lane >> 2);
    const int br = lane & 3;

    for (int t = 0; t < T; t++) {
        asm volatile("cp.async.wait_group 1;\n");
        __syncthreads();

        // prefetch stage t+2 into buffer (t+2)%3 (freed at barrier above)
        if (t + 2 < T) {
            const int k0 = (t + 2) * BK;
            const int nb = (t + 2) % STG;
            const uint32_t ao = nb * aBuf;
            const uint32_t bo = nb * bBuf;
            CP16(a_dst0 + ao, a_src0 + k0); CP16(a_dst1 + ao, a_src1 + k0);
            CP16(b_dst0 + bo, b_src0 + (size_t)k0 * N); CP16(b_dst1 + bo, b_src1 + (size_t)k0 * N);
        }
        CPCOMMIT();

        const int buf = t % STG;
        const uint32_t* As32 = (const uint32_t*)&As[buf][0];
        const uint32_t* Bs32 = (const uint32_t*)&Bs[buf][0];

        #pragma unroll
        for (int ks = 0; ks < BK; ks += 8) {
            uint32_t af[4][4];
            #pragma unroll
            for (int mt = 0; mt < 4; mt++) {
                const uint32_t* p = As32 + (ar + mt * 16) * APAD + ks + ac;
                af[mt][0] = p[0];
                af[mt][1] = p[8 * APAD];
                af[mt][2] = p[4];
                af[mt][3] = p[8 * APAD + 4];
            }
            uint32_t bf[4][2];
            #pragma unroll
            for (int nt = 0; nt < 4; nt++) {
                const uint32_t* p = Bs32 + (ks + br) * BPAD + bc + nt * 8;
                bf[nt][0] = p[0];
                bf[nt][1] = p[4 * BPAD];
            }
            #pragma unroll
            for (int mt = 0; mt < 4; mt++)
                #pragma unroll
                for (int nt = 0; nt < 4; nt++)
                    asm volatile(
                        "mma.sync.aligned.m16n8k8.row.col.f32.tf32.tf32.f32 "
                        "{%0,%1,%2,%3}, {%4,%5,%6,%7}, {%8,%9}, {%0,%1,%2,%3};\n"
                        : "+f"(acc[mt][nt][0]), "+f"(acc[mt][nt][1]),
                          "+f"(acc[mt][nt][2]), "+f"(acc[mt][nt][3])
                        : "r"(af[mt][0]), "r"(af[mt][1]), "r"(af[mt][2]), "r"(af[mt][3]),
                          "r"(bf[nt][0]), "r"(bf[nt][1]));
        }
    }

    // ---- epilogue ----
    #pragma unroll
    for (int mt = 0; mt < 4; mt++) {
        #pragma unroll
        for (int nt = 0; nt < 4; nt++) {
            const int r0 = bm + wm * 64 + mt * 16 + (lane >> 2);
            const int c  = bn + wn * 32 + nt * 8 + (lane & 3) * 2;
            const float bx = bias[c], by = bias[c + 1];
            #pragma unroll
            for (int half = 0; half < 2; half++) {
                const int r = r0 + half * 8;
                float vx = acc[mt][nt][half * 2 + 0] + bx;
                float vy = acc[mt][nt][half * 2 + 1] + by;
                if (ACT == 1) { vx = gelu_exact(vx); vy = gelu_exact(vy); }
                if (ROUND) { vx = tf32r(vx); vy = tf32r(vy); }
                if (RES) {
                    const float2 rr = *(const float2*)(R + (size_t)r * N + c);
                    vx += rr.x; vy += rr.y;
                }
                float2 o; o.x = vx; o.y = vy;
                *(float2*)(C + (size_t)r * N + c) = o;
            }
        }
    }
}

// ---------------- tiny GEMM for the 16 global tokens -----------------------
template<int ACT, bool RES>
__global__ __launch_bounds__(128)
void small_gemm(int N, int K,
                const float* __restrict__ A, const float* __restrict__ W,
                const float* __restrict__ bias, const float* __restrict__ R,
                float* __restrict__ C)
{
    const int r = blockIdx.y;
    const int n = blockIdx.x * 128 + threadIdx.x;
    const float* a = A + (size_t)r * K;
    float acc = 0.0f;
    #pragma unroll 8
    for (int k = 0; k < K; k++)
        acc = fmaf(__ldg(a + k), W[(size_t)k * N + n], acc);
    float v = acc + bias[n];
    if (ACT == 1) v = gelu_exact(v);
    if (RES) v += R[(size_t)r * N + n];
    C[(size_t)r * N + n] = v;
}

// ---------------- window attention: one block per (window, head) -----------
__global__ __launch_bounds__(128)
void win_attn(const float* __restrict__ kvq, const float* __restrict__ kvqavg,
              const float* __restrict__ table,
              const float* __restrict__ xin, float* __restrict__ x1)
{
    const int w = blockIdx.x;            // 0..1023
    const int h = blockIdx.y;            // 0..15
    const int b  = w >> 6;
    const int wi = w & 63;
    const int wr = wi >> 3, wc = wi & 7;

    __shared__ float qs[36][33];
    __shared__ float ks[37][33];
    __shared__ float vs[37][33];
    __shared__ float sc[36][37];

    const int tid = threadIdx.x;

    for (int idx = tid; idx < 36 * 32; idx += 128) {
        const int m = idx >> 5, d = idx & 31;
        const int r = m / 6, c = m % 6;
        const int l = (wr * 6 + r) * 48 + wc * 6 + c;
        const float* row = kvq + (size_t)(b * Lc + l) * NKVQ + h * 32 + d;
        ks[m][d] = row[0];
        vs[m][d] = row[DIMc];
        qs[m][d] = row[2 * DIMc] * SCALEc;
    }
    if (tid < 32) {
        const float* row = kvqavg + (size_t)b * NKVQ + h * 32 + tid;
        ks[36][tid] = row[0];
        vs[36][tid] = row[DIMc];
    }
    __syncthreads();

    for (int p = tid; p < 36 * 37; p += 128) {
        const int mq = p / 37, mk = p % 37;
        float acc = 0.0f;
        #pragma unroll
        for (int d = 0; d < 32; d++) acc = fmaf(qs[mq][d], ks[mk][d], acc);
        int d0, d1;
        if (mk == 36) { d0 = mq % 6; d1 = mq / 6; }
        else          { d0 = mq % 6 - mk % 6; d1 = mq / 6 - mk / 6; }
        const int idx = (d0 + 5) * 11 + (d1 + 5);
        sc[mq][mk] = acc + table[idx * NHc + h];
    }
    __syncthreads();

    if (tid < 36) {
        float mx = -1e30f;
        #pragma unroll
        for (int k = 0; k < 37; k++) mx = fmaxf(mx, sc[tid][k]);
        float sum = 0.0f;
        #pragma unroll
        for (int k = 0; k < 37; k++) { const float e = expf(sc[tid][k] - mx); sc[tid][k] = e; sum += e; }
        const float inv = 1.0f / sum;
        #pragma unroll
        for (int k = 0; k < 37; k++) sc[tid][k] *= inv;
    }
    __syncthreads();

    for (int idx = tid; idx < 36 * 32; idx += 128) {
        const int m = idx >> 5, d = idx & 31;
        float acc = 0.0f;
        #pragma unroll
        for (int k = 0; k < 37; k++) acc = fmaf(sc[m][k], vs[k][d], acc);
        const int r = m / 6, c = m % 6;
        const int l = (wr * 6 + r) * 48 + wc * 6 + c;
        const size_t o = (size_t)(b * Lc + l) * DIMc + h * 32 + d;
        x1[o] = xin[o] + acc;
    }
}

// ---------------- global-token attention: one block per (b, h) -------------
__global__ __launch_bounds__(256)
void glob_attn(const float* __restrict__ kvqavg, const float* __restrict__ kvq,
               const float* __restrict__ xavg_in, float* __restrict__ xavg1)
{
    const int b = blockIdx.x, h = blockIdx.y;
    __shared__ float qsh[32];
    __shared__ float wgt[Lc];
    __shared__ float red[8];
    const int tid = threadIdx.x, lane = tid & 31, wn = tid >> 5;

    if (tid < 32) qsh[tid] = kvqavg[(size_t)b * NKVQ + 2 * DIMc + h * 32 + tid] * SCALEc;
    __syncthreads();

    float lmax = -1e30f;
    for (int k = tid; k < Lc; k += 256) {
        const float4* kp = (const float4*)(kvq + (size_t)(b * Lc + k) * NKVQ + h * 32);
        float acc = 0.0f;
        #pragma unroll
        for (int d4 = 0; d4 < 8; d4++) {
            const float4 kk = kp[d4];
            acc = fmaf(qsh[d4*4+0], kk.x, acc);
            acc = fmaf(qsh[d4*4+1], kk.y, acc);
            acc = fmaf(qsh[d4*4+2], kk.z, acc);
            acc = fmaf(qsh[d4*4+3], kk.w, acc);
        }
        wgt[k] = acc;
        lmax = fmaxf(lmax, acc);
    }
    #pragma unroll
    for (int o = 16; o; o >>= 1) lmax = fmaxf(lmax, __shfl_xor_sync(0xffffffffu, lmax, o));
    if (lane == 0) red[wn] = lmax;
    __syncthreads();
    float gmax = red[0];
    #pragma unroll
    for (int i = 1; i < 8; i++) gmax = fmaxf(gmax, red[i]);
    __syncthreads();

    float lsum = 0.0f;
    for (int k = tid; k < Lc; k += 256) {
        const float e = expf(wgt[k] - gmax);
        wgt[k] = e;
        lsum += e;
    }
    #pragma unroll
    for (int o = 16; o; o >>= 1) lsum += __shfl_xor_sync(0xffffffffu, lsum, o);
    if (lane == 0) red[wn] = lsum;
    __syncthreads();
    float gsum = 0.0f;
    #pragma unroll
    for (int i = 0; i < 8; i++) gsum += red[i];
    const float inv = 1.0f / gsum;

    float acc[4] = {0.f, 0.f, 0.f, 0.f};
    for (int k = lane; k < Lc; k += 32) {
        const float wk = wgt[k];
        const float4 vv = *(const float4*)(kvq + (size_t)(b * Lc + k) * NKVQ + DIMc + h * 32 + wn * 4);
        acc[0] = fmaf(wk, vv.x, acc[0]);
        acc[1] = fmaf(wk, vv.y, acc[1]);
        acc[2] = fmaf(wk, vv.z, acc[2]);
        acc[3] = fmaf(wk, vv.w, acc[3]);
    }
    #pragma unroll
    for (int j = 0; j < 4; j++) {
        #pragma unroll
        for (int o = 16; o; o >>= 1) acc[j] += __shfl_xor_sync(0xffffffffu, acc[j], o);
    }
    if (lane == 0) {
        #pragma unroll
        for (int j = 0; j < 4; j++) {
            const size_t o = (size_t)b * DIMc + h * 32 + wn * 4 + j;
            xavg1[o] = xavg_in[o] + acc[j] * inv;
        }
    }
}

// ---------------------------------------------------------------------------
extern "C" void kernel_launch(void* const* d_in, const int* in_sizes, int n_in,
                              void* d_out, int out_size)
{
    const float* x     = (const float*)d_in[0];
    const float* xavg  = (const float*)d_in[1];
    const float* w_kv  = (const float*)d_in[2];
    const float* b_kv  = (const float*)d_in[3];
    const float* w_q   = (const float*)d_in[4];
    const float* b_q   = (const float*)d_in[5];
    const float* table = (const float*)d_in[6];
    const float* g1    = (const float*)d_in[7];
    const float* be1   = (const float*)d_in[8];
    const float* g2    = (const float*)d_in[9];
    const float* be2   = (const float*)d_in[10];
    const float* w_fc1 = (const float*)d_in[11];
    const float* b_fc1 = (const float*)d_in[12];
    const float* w_fc2 = (const float*)d_in[13];
    const float* b_fc2 = (const float*)d_in[14];
    float* out = (float*)d_out;

    float *xn, *kvq, *x1, *hbuf, *kvqavg, *xavgn, *xavg1, *havg;
    float *wkvq, *bkvq, *wfc1r, *wfc2r;
    cudaGetSymbolAddress((void**)&xn,     g_xn);
    cudaGetSymbolAddress((void**)&kvq,    g_kvq);
    cudaGetSymbolAddress((void**)&x1,     g_x1);
    cudaGetSymbolAddress((void**)&hbuf,   g_h);
    cudaGetSymbolAddress((void**)&kvqavg, g_kvqavg);
    cudaGetSymbolAddress((void**)&xavgn,  g_xavgn);
    cudaGetSymbolAddress((void**)&xavg1,  g_xavg1);
    cudaGetSymbolAddress((void**)&havg,   g_havg);
    cudaGetSymbolAddress((void**)&wkvq,   g_wkvq);
    cudaGetSymbolAddress((void**)&bkvq,   g_bkvq);
    cudaGetSymbolAddress((void**)&wfc1r,  g_wfc1r);
    cudaGetSymbolAddress((void**)&wfc2r,  g_wfc2r);

    // 0. fuse + tf32-round weights
    prep_weights<<<592, 256>>>(w_kv, b_kv, w_q, b_q, w_fc1, w_fc2,
                               wkvq, bkvq, wfc1r, wfc2r);

    // 1. LayerNorm 1 (tf32-rounded outputs feed GEMMs)
    ln_kernel<true><<<NTOK, 128>>>(x,    g1, be1, xn);
    ln_kernel<true><<<Bc,   128>>>(xavg, g1, be1, xavgn);

    // 2. Fused kvq projection (one GEMM for k|v|q)
    tgemm<0, false, false><<<dim3(NKVQ/128, NTOK/128), 256>>>(NTOK, NKVQ, DIMc, xn, wkvq, bkvq, nullptr, kvq);
    small_gemm<0, false><<<dim3(NKVQ/128, Bc), 128>>>(NKVQ, DIMc, xavgn, wkvq, bkvq, nullptr, kvqavg);

    // 3. Attention (+ residual)
    win_attn <<<dim3(Bc*NWc, NHc), 128>>>(kvq, kvqavg, table, x, x1);
    glob_attn<<<dim3(Bc,     NHc), 256>>>(kvqavg, kvq, xavg, xavg1);

    // 4. LayerNorm 2
    ln_kernel<true><<<NTOK, 128>>>(x1,    g2, be2, xn);
    ln_kernel<true><<<Bc,   128>>>(xavg1, g2, be2, xavgn);

    // 5. MLP (+ residual), final outputs
    tgemm<1, false, true ><<<dim3(HID/128,  NTOK/128), 256>>>(NTOK, HID,  DIMc, xn,   wfc1r, b_fc1, nullptr, hbuf);
    tgemm<0, true,  false><<<dim3(DIMc/128, NTOK/128), 256>>>(NTOK, DIMc, HID,  hbuf, wfc2r, b_fc2, x1, out);
    small_gemm<1, false><<<dim3(HID/128,  Bc), 128>>>(HID,  DIMc, xavgn, wfc1r, b_fc1, nullptr, havg);
    small_gemm<0, true ><<<dim3(DIMc/128, Bc), 128>>>(DIMc, HID,  havg,  wfc2r, b_fc2, xavg1, out + (size_t)NTOK * DIMc);
}

// round 7
// speedup vs baseline: 1.4660x; 1.2784x over previous
#include <cuda_runtime.h>
#include <cuda_fp16.h>
#include <math.h>
#include <stdint.h>

// Problem constants
#define Bc   16
#define NHc  16
#define DIMc 512
#define Lc   2304          // 48*48
#define NWc  64            // (48/6)^2
#define HID  2048          // 4*DIM
#define SCALEc 0.17677669529663689f   // 32^-0.5
#define NTOK (Bc*Lc)       // 36864
#define NKVQ 1536          // fused kv(1024) + q(512)

// ---------------- scratch (device globals; no allocation allowed) ----------
__device__ __half g_xnh [NTOK * DIMc];     // LN output in fp16 (GEMM A operand)
__device__ float  g_kvq [NTOK * NKVQ];     // cols 0..511 k, 512..1023 v, 1024..1535 q
__device__ float  g_x1  [NTOK * DIMc];
__device__ __half g_h   [NTOK * HID];      // MLP hidden (fp16, A of fc2)
__device__ float  g_kvqavg[Bc * NKVQ];
__device__ float  g_xavgn[Bc * DIMc];
__device__ float  g_xavg1[Bc * DIMc];
__device__ float  g_havg [Bc * HID];
// transposed ([N,K] row-major) fp16 weights
__device__ __half g_wkvqT[NKVQ * DIMc];
__device__ float  g_bkvq [NKVQ];
__device__ __half g_wfc1T[HID * DIMc];
__device__ __half g_wfc2T[DIMc * HID];

__device__ __forceinline__ float gelu_exact(float v) {
    return 0.5f * v * (1.0f + erff(v * 0.70710678118654752440f));
}

#define CP16(dst, src) \
    asm volatile("cp.async.cg.shared.global [%0], [%1], 16;\n" :: "r"(dst), "l"(src))
#define CPCOMMIT() asm volatile("cp.async.commit_group;\n")

// ---------------- weight prep: tiled transpose + fp16 convert --------------
// src[K,N] float row-major -> dst[N,K] half row-major
__global__ __launch_bounds__(256)
void transpose_half(const float* __restrict__ src, __half* __restrict__ dst,
                    int K, int N)
{
    __shared__ float tile[32][33];
    const int kb = blockIdx.y * 32, nb = blockIdx.x * 32;
    const int tx = threadIdx.x, ty = threadIdx.y;
    #pragma unroll
    for (int i = ty; i < 32; i += 8)
        tile[i][tx] = src[(size_t)(kb + i) * N + nb + tx];
    __syncthreads();
    #pragma unroll
    for (int i = ty; i < 32; i += 8)
        dst[(size_t)(nb + i) * K + kb + tx] = __float2half_rn(tile[tx][i]);
}

__global__ void fuse_bias(const float* __restrict__ b_kv, const float* __restrict__ b_q,
                          float* __restrict__ bkvq)
{
    const int i = blockIdx.x * blockDim.x + threadIdx.x;
    if (i < NKVQ) bkvq[i] = (i < 2 * DIMc) ? b_kv[i] : b_q[i - 2 * DIMc];
}

// ---------------- LayerNorm over DIM=512, one block per token --------------
// fp32 output variant (feeds the small fp32 GEMMs for the 16 global tokens)
__global__ __launch_bounds__(128)
void ln_kernel_f(const float* __restrict__ x, const float* __restrict__ g,
                 const float* __restrict__ be, float* __restrict__ y)
{
    __shared__ float sS[4], sQ[4];
    const int t = blockIdx.x;
    const int tid = threadIdx.x;
    const float4 v = ((const float4*)(x + (size_t)t * DIMc))[tid];
    float s = v.x + v.y + v.z + v.w;
    float q = v.x*v.x + v.y*v.y + v.z*v.z + v.w*v.w;
    #pragma unroll
    for (int o = 16; o; o >>= 1) {
        s += __shfl_xor_sync(0xffffffffu, s, o);
        q += __shfl_xor_sync(0xffffffffu, q, o);
    }
    if ((tid & 31) == 0) { sS[tid >> 5] = s; sQ[tid >> 5] = q; }
    __syncthreads();
    const float S = sS[0] + sS[1] + sS[2] + sS[3];
    const float Q = sQ[0] + sQ[1] + sQ[2] + sQ[3];
    const float mean = S * (1.0f / 512.0f);
    const float var  = Q * (1.0f / 512.0f) - mean * mean;
    const float rstd = rsqrtf(var + 1e-3f);
    const float4 gg = ((const float4*)g)[tid];
    const float4 bb = ((const float4*)be)[tid];
    float4 o;
    o.x = (v.x - mean) * rstd * gg.x + bb.x;
    o.y = (v.y - mean) * rstd * gg.y + bb.y;
    o.z = (v.z - mean) * rstd * gg.z + bb.z;
    o.w = (v.w - mean) * rstd * gg.w + bb.w;
    ((float4*)(y + (size_t)t * DIMc))[tid] = o;
}

// fp16 output variant (feeds tensor-core GEMMs)
__global__ __launch_bounds__(128)
void ln_kernel_h(const float* __restrict__ x, const float* __restrict__ g,
                 const float* __restrict__ be, __half* __restrict__ y)
{
    __shared__ float sS[4], sQ[4];
    const int t = blockIdx.x;
    const int tid = threadIdx.x;
    const float4 v = ((const float4*)(x + (size_t)t * DIMc))[tid];
    float s = v.x + v.y + v.z + v.w;
    float q = v.x*v.x + v.y*v.y + v.z*v.z + v.w*v.w;
    #pragma unroll
    for (int o = 16; o; o >>= 1) {
        s += __shfl_xor_sync(0xffffffffu, s, o);
        q += __shfl_xor_sync(0xffffffffu, q, o);
    }
    if ((tid & 31) == 0) { sS[tid >> 5] = s; sQ[tid >> 5] = q; }
    __syncthreads();
    const float S = sS[0] + sS[1] + sS[2] + sS[3];
    const float Q = sQ[0] + sQ[1] + sQ[2] + sQ[3];
    const float mean = S * (1.0f / 512.0f);
    const float var  = Q * (1.0f / 512.0f) - mean * mean;
    const float rstd = rsqrtf(var + 1e-3f);
    const float4 gg = ((const float4*)g)[tid];
    const float4 bb = ((const float4*)be)[tid];
    __half2 h0 = __floats2half2_rn((v.x - mean) * rstd * gg.x + bb.x,
                                   (v.y - mean) * rstd * gg.y + bb.y);
    __half2 h1 = __floats2half2_rn((v.z - mean) * rstd * gg.z + bb.z,
                                   (v.w - mean) * rstd * gg.w + bb.w);
    __half2* yp = (__half2*)(y + (size_t)t * DIMc);
    yp[tid * 2 + 0] = h0;
    yp[tid * 2 + 1] = h1;
}

// ---------------- fp16 tensor-core GEMM (3-stage cp.async pipeline) --------
// C[M,N] = act(A[M,K]h @ WT[N,K]h^T + bias)(+R). 128x128 tile, BK=32 halfs,
// 256 threads, 2x4 warps (64x32/warp), mma.m16n8k16.f16.f32.
template<int ACT, bool RES, bool OUTH>
__global__ __launch_bounds__(256, 2)
void hgemm(int M, int N, int K,
           const __half* __restrict__ A, const __half* __restrict__ WT,
           const float* __restrict__ bias, const float* __restrict__ R,
           void* __restrict__ Cv)
{
    constexpr int BM = 128, BN = 128, BK = 32;   // BK in halfs
    constexpr int PAD = 40;                       // halfs per smem row
    constexpr int STG = 3;

    __shared__ __half As[STG][BM * PAD];
    __shared__ __half Bs[STG][BN * PAD];

    const int tid  = threadIdx.x;
    const int lane = tid & 31;
    const int warp = tid >> 5;
    const int wm   = warp >> 2;          // 0..1
    const int wn   = warp & 3;           // 0..3
    const int bm   = blockIdx.y * BM;
    const int bn   = blockIdx.x * BN;

    // load mapping: 128 rows x 64 bytes per tile; thread: row=tid/2, 32B half
    const int l_r = tid >> 1;
    const int l_o = (tid & 1) << 4;      // half offset 0 or 16
    const __half* a_src = A  + (size_t)(bm + l_r) * K + l_o;
    const __half* b_src = WT + (size_t)(bn + l_r) * K + l_o;

    const uint32_t sA0 = (uint32_t)__cvta_generic_to_shared(&As[0][0]);
    const uint32_t sB0 = (uint32_t)__cvta_generic_to_shared(&Bs[0][0]);
    const uint32_t a_dst = sA0 + (uint32_t)(l_r * PAD + l_o) * 2u;
    const uint32_t b_dst = sB0 + (uint32_t)(l_r * PAD + l_o) * 2u;
    const uint32_t STRIDE = (uint32_t)(BM * PAD) * 2u;   // bytes per stage

    float acc[4][4][4] = {};
    const int T = K / BK;

    // prologue: stages 0 and 1
    {
        CP16(a_dst, a_src); CP16(a_dst + 16u, a_src + 8);
        CP16(b_dst, b_src); CP16(b_dst + 16u, b_src + 8);
        CPCOMMIT();
        CP16(a_dst + STRIDE, a_src + BK); CP16(a_dst + STRIDE + 16u, a_src + BK + 8);
        CP16(b_dst + STRIDE, b_src + BK); CP16(b_dst + STRIDE + 16u, b_src + BK + 8);
        CPCOMMIT();
    }

    const int ar = wm * 64 + (lane >> 2);   // A row within tile
    const int ac = (lane & 3) << 1;         // A col (halfs)
    const int bq = lane >> 2;               // B row-within-8
    const int bkc = (lane & 3) << 1;        // B col (halfs)

    for (int t = 0; t < T; t++) {
        asm volatile("cp.async.wait_group 1;\n");
        __syncthreads();

        if (t + 2 < T) {
            const int k0 = (t + 2) * BK;
            const int nb = (t + 2) % STG;
            const uint32_t o = nb * STRIDE;
            CP16(a_dst + o, a_src + k0); CP16(a_dst + o + 16u, a_src + k0 + 8);
            CP16(b_dst + o, b_src + k0); CP16(b_dst + o + 16u, b_src + k0 + 8);
        }
        CPCOMMIT();

        const int buf = t % STG;
        const __half* Ash = &As[buf][0];
        const __half* Bsh = &Bs[buf][0];

        #pragma unroll
        for (int ks = 0; ks < BK; ks += 16) {
            uint32_t af[4][4];
            #pragma unroll
            for (int mt = 0; mt < 4; mt++) {
                const __half* p = Ash + (ar + mt * 16) * PAD + ks + ac;
                af[mt][0] = *(const uint32_t*)(p);
                af[mt][1] = *(const uint32_t*)(p + 8 * PAD);
                af[mt][2] = *(const uint32_t*)(p + 8);
                af[mt][3] = *(const uint32_t*)(p + 8 * PAD + 8);
            }
            uint32_t bf[4][2];
            #pragma unroll
            for (int nt = 0; nt < 4; nt++) {
                const __half* p = Bsh + (wn * 32 + nt * 8 + bq) * PAD + ks + bkc;
                bf[nt][0] = *(const uint32_t*)(p);
                bf[nt][1] = *(const uint32_t*)(p + 8);
            }
            #pragma unroll
            for (int mt = 0; mt < 4; mt++)
                #pragma unroll
                for (int nt = 0; nt < 4; nt++)
                    asm volatile(
                        "mma.sync.aligned.m16n8k16.row.col.f32.f16.f16.f32 "
                        "{%0,%1,%2,%3}, {%4,%5,%6,%7}, {%8,%9}, {%0,%1,%2,%3};\n"
                        : "+f"(acc[mt][nt][0]), "+f"(acc[mt][nt][1]),
                          "+f"(acc[mt][nt][2]), "+f"(acc[mt][nt][3])
                        : "r"(af[mt][0]), "r"(af[mt][1]), "r"(af[mt][2]), "r"(af[mt][3]),
                          "r"(bf[nt][0]), "r"(bf[nt][1]));
        }
    }

    // ---- epilogue ----
    float* Cf = (float*)Cv;
    __half* Ch = (__half*)Cv;
    #pragma unroll
    for (int mt = 0; mt < 4; mt++) {
        #pragma unroll
        for (int nt = 0; nt < 4; nt++) {
            const int r0 = bm + wm * 64 + mt * 16 + (lane >> 2);
            const int c  = bn + wn * 32 + nt * 8 + (lane & 3) * 2;
            const float bx = bias[c], by = bias[c + 1];
            #pragma unroll
            for (int half_ = 0; half_ < 2; half_++) {
                const int r = r0 + half_ * 8;
                float vx = acc[mt][nt][half_ * 2 + 0] + bx;
                float vy = acc[mt][nt][half_ * 2 + 1] + by;
                if (ACT == 1) { vx = gelu_exact(vx); vy = gelu_exact(vy); }
                if (RES) {
                    const float2 rr = *(const float2*)(R + (size_t)r * N + c);
                    vx += rr.x; vy += rr.y;
                }
                if (OUTH) {
                    *(__half2*)(Ch + (size_t)r * N + c) = __floats2half2_rn(vx, vy);
                } else {
                    float2 o; o.x = vx; o.y = vy;
                    *(float2*)(Cf + (size_t)r * N + c) = o;
                }
            }
        }
    }
}

// ---------------- tiny GEMM for the 16 global tokens (fp32) ----------------
template<int ACT, bool RES>
__global__ __launch_bounds__(128)
void small_gemm(int N, int K, int ldC,
                const float* __restrict__ A, const float* __restrict__ W,
                const float* __restrict__ bias, const float* __restrict__ R,
                float* __restrict__ C)
{
    const int r = blockIdx.y;
    const int n = blockIdx.x * 128 + threadIdx.x;
    const float* a = A + (size_t)r * K;
    float acc = 0.0f;
    #pragma unroll 8
    for (int k = 0; k < K; k++)
        acc = fmaf(__ldg(a + k), W[(size_t)k * N + n], acc);
    float v = acc + bias[n];
    if (ACT == 1) v = gelu_exact(v);
    if (RES) v += R[(size_t)r * ldC + n];
    C[(size_t)r * ldC + n] = v;
}

// ---------------- window attention: one block per (window, head) -----------
__global__ __launch_bounds__(128)
void win_attn(const float* __restrict__ kvq, const float* __restrict__ kvqavg,
              const float* __restrict__ table,
              const float* __restrict__ xin, float* __restrict__ x1)
{
    const int w = blockIdx.x;            // 0..1023
    const int h = blockIdx.y;            // 0..15
    const int b  = w >> 6;
    const int wi = w & 63;
    const int wr = wi >> 3, wc = wi & 7;

    __shared__ float qs[36][33];
    __shared__ float ks[37][33];
    __shared__ float vs[37][33];
    __shared__ float sc[36][37];

    const int tid = threadIdx.x;

    for (int idx = tid; idx < 36 * 32; idx += 128) {
        const int m = idx >> 5, d = idx & 31;
        const int r = m / 6, c = m % 6;
        const int l = (wr * 6 + r) * 48 + wc * 6 + c;
        const float* row = kvq + (size_t)(b * Lc + l) * NKVQ + h * 32 + d;
        ks[m][d] = row[0];
        vs[m][d] = row[DIMc];
        qs[m][d] = row[2 * DIMc] * SCALEc;
    }
    if (tid < 32) {
        const float* row = kvqavg + (size_t)b * NKVQ + h * 32 + tid;
        ks[36][tid] = row[0];
        vs[36][tid] = row[DIMc];
    }
    __syncthreads();

    for (int p = tid; p < 36 * 37; p += 128) {
        const int mq = p / 37, mk = p % 37;
        float acc = 0.0f;
        #pragma unroll
        for (int d = 0; d < 32; d++) acc = fmaf(qs[mq][d], ks[mk][d], acc);
        int d0, d1;
        if (mk == 36) { d0 = mq % 6; d1 = mq / 6; }
        else          { d0 = mq % 6 - mk % 6; d1 = mq / 6 - mk / 6; }
        const int idx = (d0 + 5) * 11 + (d1 + 5);
        sc[mq][mk] = acc + table[idx * NHc + h];
    }
    __syncthreads();

    if (tid < 36) {
        float mx = -1e30f;
        #pragma unroll
        for (int k = 0; k < 37; k++) mx = fmaxf(mx, sc[tid][k]);
        float sum = 0.0f;
        #pragma unroll
        for (int k = 0; k < 37; k++) { const float e = expf(sc[tid][k] - mx); sc[tid][k] = e; sum += e; }
        const float inv = 1.0f / sum;
        #pragma unroll
        for (int k = 0; k < 37; k++) sc[tid][k] *= inv;
    }
    __syncthreads();

    for (int idx = tid; idx < 36 * 32; idx += 128) {
        const int m = idx >> 5, d = idx & 31;
        float acc = 0.0f;
        #pragma unroll
        for (int k = 0; k < 37; k++) acc = fmaf(sc[m][k], vs[k][d], acc);
        const int r = m / 6, c = m % 6;
        const int l = (wr * 6 + r) * 48 + wc * 6 + c;
        const size_t o = (size_t)(b * Lc + l) * DIMc + h * 32 + d;
        x1[o] = xin[o] + acc;
    }
}

// ---------------- global-token attention: one block per (b, h) -------------
__global__ __launch_bounds__(256)
void glob_attn(const float* __restrict__ kvqavg, const float* __restrict__ kvq,
               const float* __restrict__ xavg_in, float* __restrict__ xavg1)
{
    const int b = blockIdx.x, h = blockIdx.y;
    __shared__ float qsh[32];
    __shared__ float wgt[Lc];
    __shared__ float red[8];
    const int tid = threadIdx.x, lane = tid & 31, wn = tid >> 5;

    if (tid < 32) qsh[tid] = kvqavg[(size_t)b * NKVQ + 2 * DIMc + h * 32 + tid] * SCALEc;
    __syncthreads();

    float lmax = -1e30f;
    for (int k = tid; k < Lc; k += 256) {
        const float4* kp = (const float4*)(kvq + (size_t)(b * Lc + k) * NKVQ + h * 32);
        float acc = 0.0f;
        #pragma unroll
        for (int d4 = 0; d4 < 8; d4++) {
            const float4 kk = kp[d4];
            acc = fmaf(qsh[d4*4+0], kk.x, acc);
            acc = fmaf(qsh[d4*4+1], kk.y, acc);
            acc = fmaf(qsh[d4*4+2], kk.z, acc);
            acc = fmaf(qsh[d4*4+3], kk.w, acc);
        }
        wgt[k] = acc;
        lmax = fmaxf(lmax, acc);
    }
    #pragma unroll
    for (int o = 16; o; o >>= 1) lmax = fmaxf(lmax, __shfl_xor_sync(0xffffffffu, lmax, o));
    if (lane == 0) red[wn] = lmax;
    __syncthreads();
    float gmax = red[0];
    #pragma unroll
    for (int i = 1; i < 8; i++) gmax = fmaxf(gmax, red[i]);
    __syncthreads();

    float lsum = 0.0f;
    for (int k = tid; k < Lc; k += 256) {
        const float e = expf(wgt[k] - gmax);
        wgt[k] = e;
        lsum += e;
    }
    #pragma unroll
    for (int o = 16; o; o >>= 1) lsum += __shfl_xor_sync(0xffffffffu, lsum, o);
    if (lane == 0) red[wn] = lsum;
    __syncthreads();
    float gsum = 0.0f;
    #pragma unroll
    for (int i = 0; i < 8; i++) gsum += red[i];
    const float inv = 1.0f / gsum;

    float acc[4] = {0.f, 0.f, 0.f, 0.f};
    for (int k = lane; k < Lc; k += 32) {
        const float wk = wgt[k];
        const float4 vv = *(const float4*)(kvq + (size_t)(b * Lc + k) * NKVQ + DIMc + h * 32 + wn * 4);
        acc[0] = fmaf(wk, vv.x, acc[0]);
        acc[1] = fmaf(wk, vv.y, acc[1]);
        acc[2] = fmaf(wk, vv.z, acc[2]);
        acc[3] = fmaf(wk, vv.w, acc[3]);
    }
    #pragma unroll
    for (int j = 0; j < 4; j++) {
        #pragma unroll
        for (int o = 16; o; o >>= 1) acc[j] += __shfl_xor_sync(0xffffffffu, acc[j], o);
    }
    if (lane == 0) {
        #pragma unroll
        for (int j = 0; j < 4; j++) {
            const size_t o = (size_t)b * DIMc + h * 32 + wn * 4 + j;
            xavg1[o] = xavg_in[o] + acc[j] * inv;
        }
    }
}

// ---------------------------------------------------------------------------
extern "C" void kernel_launch(void* const* d_in, const int* in_sizes, int n_in,
                              void* d_out, int out_size)
{
    const float* x     = (const float*)d_in[0];
    const float* xavg  = (const float*)d_in[1];
    const float* w_kv  = (const float*)d_in[2];
    const float* b_kv  = (const float*)d_in[3];
    const float* w_q   = (const float*)d_in[4];
    const float* b_q   = (const float*)d_in[5];
    const float* table = (const float*)d_in[6];
    const float* g1    = (const float*)d_in[7];
    const float* be1   = (const float*)d_in[8];
    const float* g2    = (const float*)d_in[9];
    const float* be2   = (const float*)d_in[10];
    const float* w_fc1 = (const float*)d_in[11];
    const float* b_fc1 = (const float*)d_in[12];
    const float* w_fc2 = (const float*)d_in[13];
    const float* b_fc2 = (const float*)d_in[14];
    float* out = (float*)d_out;

    __half *xnh, *hbuf, *wkvqT, *wfc1T, *wfc2T;
    float *kvq, *x1, *kvqavg, *xavgn, *xavg1, *havg, *bkvq;
    cudaGetSymbolAddress((void**)&xnh,    g_xnh);
    cudaGetSymbolAddress((void**)&kvq,    g_kvq);
    cudaGetSymbolAddress((void**)&x1,     g_x1);
    cudaGetSymbolAddress((void**)&hbuf,   g_h);
    cudaGetSymbolAddress((void**)&kvqavg, g_kvqavg);
    cudaGetSymbolAddress((void**)&xavgn,  g_xavgn);
    cudaGetSymbolAddress((void**)&xavg1,  g_xavg1);
    cudaGetSymbolAddress((void**)&havg,   g_havg);
    cudaGetSymbolAddress((void**)&wkvqT,  g_wkvqT);
    cudaGetSymbolAddress((void**)&bkvq,   g_bkvq);
    cudaGetSymbolAddress((void**)&wfc1T,  g_wfc1T);
    cudaGetSymbolAddress((void**)&wfc2T,  g_wfc2T);

    // 0. weight prep: transpose to [N,K] + fp16; fuse kv|q bias
    transpose_half<<<dim3(1024/32, 512/32),  dim3(32, 8)>>>(w_kv,  wkvqT,              512, 1024);
    transpose_half<<<dim3( 512/32, 512/32),  dim3(32, 8)>>>(w_q,   wkvqT + 1024 * 512, 512,  512);
    transpose_half<<<dim3(2048/32, 512/32),  dim3(32, 8)>>>(w_fc1, wfc1T,              512, 2048);
    transpose_half<<<dim3( 512/32, 2048/32), dim3(32, 8)>>>(w_fc2, wfc2T,             2048,  512);
    fuse_bias<<<6, 256>>>(b_kv, b_q, bkvq);

    // 1. LayerNorm 1
    ln_kernel_h<<<NTOK, 128>>>(x,    g1, be1, xnh);
    ln_kernel_f<<<Bc,   128>>>(xavg, g1, be1, xavgn);

    // 2. Fused kvq projection (fp16 tensor cores)
    hgemm<0, false, false><<<dim3(NKVQ/128, NTOK/128), 256>>>(NTOK, NKVQ, DIMc, xnh, wkvqT, bkvq, nullptr, kvq);
    small_gemm<0, false><<<dim3(1024/128, Bc), 128>>>(1024, DIMc, NKVQ, xavgn, w_kv, b_kv, nullptr, kvqavg);
    small_gemm<0, false><<<dim3( 512/128, Bc), 128>>>( 512, DIMc, NKVQ, xavgn, w_q,  b_q,  nullptr, kvqavg + 2 * DIMc);

    // 3. Attention (+ residual)
    win_attn <<<dim3(Bc*NWc, NHc), 128>>>(kvq, kvqavg, table, x, x1);
    glob_attn<<<dim3(Bc,     NHc), 256>>>(kvqavg, kvq, xavg, xavg1);

    // 4. LayerNorm 2
    ln_kernel_h<<<NTOK, 128>>>(x1,    g2, be2, xnh);
    ln_kernel_f<<<Bc,   128>>>(xavg1, g2, be2, xavgn);

    // 5. MLP (+ residual), final outputs
    hgemm<1, false, true ><<<dim3(HID/128,  NTOK/128), 256>>>(NTOK, HID,  DIMc, xnh,  wfc1T, b_fc1, nullptr, hbuf);
    hgemm<0, true,  false><<<dim3(DIMc/128, NTOK/128), 256>>>(NTOK, DIMc, HID,  hbuf, wfc2T, b_fc2, x1, out);
    small_gemm<1, false><<<dim3(HID/128,  Bc), 128>>>(HID,  DIMc, HID,  xavgn, w_fc1, b_fc1, nullptr, havg);
    small_gemm<0, true ><<<dim3(DIMc/128, Bc), 128>>>(DIMc, HID,  DIMc, havg,  w_fc2, b_fc2, xavg1, out + (size_t)NTOK * DIMc);
}

// round 8
// speedup vs baseline: 1.5507x; 1.0578x over previous
#include <cuda_runtime.h>
#include <cuda_fp16.h>
#include <math.h>
#include <stdint.h>

// Problem constants
#define Bc   16
#define NHc  16
#define DIMc 512
#define Lc   2304          // 48*48
#define NWc  64            // (48/6)^2
#define HID  2048          // 4*DIM
#define SCALEc 0.17677669529663689f   // 32^-0.5
#define NTOK (Bc*Lc)       // 36864
#define NKVQ 1536          // fused kv(1024) + q(512)

// ---------------- scratch (device globals; no allocation allowed) ----------
__device__ __half g_xnh [NTOK * DIMc];     // LN output in fp16 (GEMM A operand)
__device__ __half g_kvqh[NTOK * NKVQ];     // cols 0..511 k, 512..1023 v, 1024..1535 q
__device__ float  g_x1  [NTOK * DIMc];
__device__ __half g_h   [NTOK * HID];      // MLP hidden (fp16, A of fc2)
__device__ float  g_kvqavg[Bc * NKVQ];
__device__ float  g_xavgn[Bc * DIMc];
__device__ float  g_xavg1[Bc * DIMc];
__device__ float  g_havg [Bc * HID];
// transposed ([N,K] row-major) fp16 weights
__device__ __half g_wkvqT[NKVQ * DIMc];
__device__ float  g_bkvq [NKVQ];
__device__ __half g_wfc1T[HID * DIMc];
__device__ __half g_wfc2T[DIMc * HID];

__device__ __forceinline__ float gelu_exact(float v) {
    return 0.5f * v * (1.0f + erff(v * 0.70710678118654752440f));
}

#define CP16(dst, src) \
    asm volatile("cp.async.cg.shared.global [%0], [%1], 16;\n" :: "r"(dst), "l"(src))
#define CPCOMMIT() asm volatile("cp.async.commit_group;\n")
#define LDSM4(r0, r1, r2, r3, addr) \
    asm volatile("ldmatrix.sync.aligned.m8n8.x4.shared.b16 {%0,%1,%2,%3}, [%4];" \
                 : "=r"(r0), "=r"(r1), "=r"(r2), "=r"(r3) : "r"(addr))

// ---------------- weight prep: tiled transpose + fp16 convert --------------
__global__ __launch_bounds__(256)
void transpose_half(const float* __restrict__ src, __half* __restrict__ dst,
                    int K, int N)
{
    __shared__ float tile[32][33];
    const int kb = blockIdx.y * 32, nb = blockIdx.x * 32;
    const int tx = threadIdx.x, ty = threadIdx.y;
    #pragma unroll
    for (int i = ty; i < 32; i += 8)
        tile[i][tx] = src[(size_t)(kb + i) * N + nb + tx];
    __syncthreads();
    #pragma unroll
    for (int i = ty; i < 32; i += 8)
        dst[(size_t)(nb + i) * K + kb + tx] = __float2half_rn(tile[tx][i]);
}

__global__ void fuse_bias(const float* __restrict__ b_kv, const float* __restrict__ b_q,
                          float* __restrict__ bkvq)
{
    const int i = blockIdx.x * blockDim.x + threadIdx.x;
    if (i < NKVQ) bkvq[i] = (i < 2 * DIMc) ? b_kv[i] : b_q[i - 2 * DIMc];
}

// ---------------- LayerNorm over DIM=512, one block per token --------------
__global__ __launch_bounds__(128)
void ln_kernel_f(const float* __restrict__ x, const float* __restrict__ g,
                 const float* __restrict__ be, float* __restrict__ y)
{
    __shared__ float sS[4], sQ[4];
    const int t = blockIdx.x;
    const int tid = threadIdx.x;
    const float4 v = ((const float4*)(x + (size_t)t * DIMc))[tid];
    float s = v.x + v.y + v.z + v.w;
    float q = v.x*v.x + v.y*v.y + v.z*v.z + v.w*v.w;
    #pragma unroll
    for (int o = 16; o; o >>= 1) {
        s += __shfl_xor_sync(0xffffffffu, s, o);
        q += __shfl_xor_sync(0xffffffffu, q, o);
    }
    if ((tid & 31) == 0) { sS[tid >> 5] = s; sQ[tid >> 5] = q; }
    __syncthreads();
    const float S = sS[0] + sS[1] + sS[2] + sS[3];
    const float Q = sQ[0] + sQ[1] + sQ[2] + sQ[3];
    const float mean = S * (1.0f / 512.0f);
    const float var  = Q * (1.0f / 512.0f) - mean * mean;
    const float rstd = rsqrtf(var + 1e-3f);
    const float4 gg = ((const float4*)g)[tid];
    const float4 bb = ((const float4*)be)[tid];
    float4 o;
    o.x = (v.x - mean) * rstd * gg.x + bb.x;
    o.y = (v.y - mean) * rstd * gg.y + bb.y;
    o.z = (v.z - mean) * rstd * gg.z + bb.z;
    o.w = (v.w - mean) * rstd * gg.w + bb.w;
    ((float4*)(y + (size_t)t * DIMc))[tid] = o;
}

__global__ __launch_bounds__(128)
void ln_kernel_h(const float* __restrict__ x, const float* __restrict__ g,
                 const float* __restrict__ be, __half* __restrict__ y)
{
    __shared__ float sS[4], sQ[4];
    const int t = blockIdx.x;
    const int tid = threadIdx.x;
    const float4 v = ((const float4*)(x + (size_t)t * DIMc))[tid];
    float s = v.x + v.y + v.z + v.w;
    float q = v.x*v.x + v.y*v.y + v.z*v.z + v.w*v.w;
    #pragma unroll
    for (int o = 16; o; o >>= 1) {
        s += __shfl_xor_sync(0xffffffffu, s, o);
        q += __shfl_xor_sync(0xffffffffu, q, o);
    }
    if ((tid & 31) == 0) { sS[tid >> 5] = s; sQ[tid >> 5] = q; }
    __syncthreads();
    const float S = sS[0] + sS[1] + sS[2] + sS[3];
    const float Q = sQ[0] + sQ[1] + sQ[2] + sQ[3];
    const float mean = S * (1.0f / 512.0f);
    const float var  = Q * (1.0f / 512.0f) - mean * mean;
    const float rstd = rsqrtf(var + 1e-3f);
    const float4 gg = ((const float4*)g)[tid];
    const float4 bb = ((const float4*)be)[tid];
    __half2 h0 = __floats2half2_rn((v.x - mean) * rstd * gg.x + bb.x,
                                   (v.y - mean) * rstd * gg.y + bb.y);
    __half2 h1 = __floats2half2_rn((v.z - mean) * rstd * gg.z + bb.z,
                                   (v.w - mean) * rstd * gg.w + bb.w);
    __half2* yp = (__half2*)(y + (size_t)t * DIMc);
    yp[tid * 2 + 0] = h0;
    yp[tid * 2 + 1] = h1;
}

// ---------------- fp16 tensor-core GEMM (ldmatrix + 3-stage cp.async) ------
// C[M,N] = act(A[M,K]h @ WT[N,K]h^T + bias)(+R). 128x128 tile, BK=32 halfs,
// 256 threads, 2x4 warps (64x32/warp), mma.m16n8k16.f16.f32, LDSM fragments.
template<int ACT, bool RES, bool OUTH>
__global__ __launch_bounds__(256, 2)
void hgemm(int M, int N, int K,
           const __half* __restrict__ A, const __half* __restrict__ WT,
           const float* __restrict__ bias, const float* __restrict__ R,
           void* __restrict__ Cv)
{
    constexpr int BM = 128, BN = 128, BK = 32;   // BK in halfs
    constexpr int PAD = 40;                       // halfs per smem row
    constexpr int STG = 3;

    __shared__ __half As[STG][BM * PAD];
    __shared__ __half Bs[STG][BN * PAD];

    const int tid  = threadIdx.x;
    const int lane = tid & 31;
    const int warp = tid >> 5;
    const int wm   = warp >> 2;          // 0..1
    const int wn   = warp & 3;           // 0..3
    const int bm   = blockIdx.y * BM;
    const int bn   = blockIdx.x * BN;

    // load mapping: 128 rows x 64 bytes per tile; thread: row=tid/2
    const int l_r = tid >> 1;
    const int l_o = (tid & 1) << 4;      // half offset 0 or 16
    const __half* a_src = A  + (size_t)(bm + l_r) * K + l_o;
    const __half* b_src = WT + (size_t)(bn + l_r) * K + l_o;

    const uint32_t sA0 = (uint32_t)__cvta_generic_to_shared(&As[0][0]);
    const uint32_t sB0 = (uint32_t)__cvta_generic_to_shared(&Bs[0][0]);
    const uint32_t a_dst = sA0 + (uint32_t)(l_r * PAD + l_o) * 2u;
    const uint32_t b_dst = sB0 + (uint32_t)(l_r * PAD + l_o) * 2u;
    const uint32_t STRIDE = (uint32_t)(BM * PAD) * 2u;   // bytes per stage

    // ldmatrix base addresses (stage 0)
    // A, per mt: row = wm*64 + mt*16 + (lane&15), col = (lane>>4)*8
    uint32_t aLd[4];
    #pragma unroll
    for (int mt = 0; mt < 4; mt++) {
        const int row = wm * 64 + mt * 16 + (lane & 15);
        const int col = (lane >> 4) * 8;
        aLd[mt] = sA0 + (uint32_t)(row * PAD + col) * 2u;
    }
    // B, per ng (16-n group): row = wn*32 + ng*16 + (lane&7) + (lane>>4)*8,
    //                         col = ((lane>>3)&1)*8
    uint32_t bLd[2];
    #pragma unroll
    for (int ng = 0; ng < 2; ng++) {
        const int row = wn * 32 + ng * 16 + (lane & 7) + (lane >> 4) * 8;
        const int col = ((lane >> 3) & 1) * 8;
        bLd[ng] = sB0 + (uint32_t)(row * PAD + col) * 2u;
    }

    float acc[4][4][4] = {};
    const int T = K / BK;

    // prologue: stages 0 and 1
    {
        CP16(a_dst, a_src); CP16(a_dst + 16u, a_src + 8);
        CP16(b_dst, b_src); CP16(b_dst + 16u, b_src + 8);
        CPCOMMIT();
        CP16(a_dst + STRIDE, a_src + BK); CP16(a_dst + STRIDE + 16u, a_src + BK + 8);
        CP16(b_dst + STRIDE, b_src + BK); CP16(b_dst + STRIDE + 16u, b_src + BK + 8);
        CPCOMMIT();
    }

    for (int t = 0; t < T; t++) {
        asm volatile("cp.async.wait_group 1;\n");
        __syncthreads();

        if (t + 2 < T) {
            const int k0 = (t + 2) * BK;
            const int nb = (t + 2) % STG;
            const uint32_t o = nb * STRIDE;
            CP16(a_dst + o, a_src + k0); CP16(a_dst + o + 16u, a_src + k0 + 8);
            CP16(b_dst + o, b_src + k0); CP16(b_dst + o + 16u, b_src + k0 + 8);
        }
        CPCOMMIT();

        const uint32_t so = (uint32_t)(t % STG) * STRIDE;

        #pragma unroll
        for (int ks = 0; ks < BK; ks += 16) {
            uint32_t af[4][4];
            #pragma unroll
            for (int mt = 0; mt < 4; mt++)
                LDSM4(af[mt][0], af[mt][1], af[mt][2], af[mt][3],
                      aLd[mt] + so + (uint32_t)ks * 2u);
            uint32_t bf[4][2];
            #pragma unroll
            for (int ng = 0; ng < 2; ng++)
                LDSM4(bf[2*ng][0], bf[2*ng][1], bf[2*ng+1][0], bf[2*ng+1][1],
                      bLd[ng] + so + (uint32_t)ks * 2u);
            #pragma unroll
            for (int mt = 0; mt < 4; mt++)
                #pragma unroll
                for (int nt = 0; nt < 4; nt++)
                    asm volatile(
                        "mma.sync.aligned.m16n8k16.row.col.f32.f16.f16.f32 "
                        "{%0,%1,%2,%3}, {%4,%5,%6,%7}, {%8,%9}, {%0,%1,%2,%3};\n"
                        : "+f"(acc[mt][nt][0]), "+f"(acc[mt][nt][1]),
                          "+f"(acc[mt][nt][2]), "+f"(acc[mt][nt][3])
                        : "r"(af[mt][0]), "r"(af[mt][1]), "r"(af[mt][2]), "r"(af[mt][3]),
                          "r"(bf[nt][0]), "r"(bf[nt][1]));
        }
    }

    // ---- epilogue ----
    float* Cf = (float*)Cv;
    __half* Ch = (__half*)Cv;
    #pragma unroll
    for (int mt = 0; mt < 4; mt++) {
        #pragma unroll
        for (int nt = 0; nt < 4; nt++) {
            const int r0 = bm + wm * 64 + mt * 16 + (lane >> 2);
            const int c  = bn + wn * 32 + nt * 8 + (lane & 3) * 2;
            const float bx = bias[c], by = bias[c + 1];
            #pragma unroll
            for (int half_ = 0; half_ < 2; half_++) {
                const int r = r0 + half_ * 8;
                float vx = acc[mt][nt][half_ * 2 + 0] + bx;
                float vy = acc[mt][nt][half_ * 2 + 1] + by;
                if (ACT == 1) { vx = gelu_exact(vx); vy = gelu_exact(vy); }
                if (RES) {
                    const float2 rr = *(const float2*)(R + (size_t)r * N + c);
                    vx += rr.x; vy += rr.y;
                }
                if (OUTH) {
                    *(__half2*)(Ch + (size_t)r * N + c) = __floats2half2_rn(vx, vy);
                } else {
                    float2 o; o.x = vx; o.y = vy;
                    *(float2*)(Cf + (size_t)r * N + c) = o;
                }
            }
        }
    }
}

// ---------------- tiny GEMM for the 16 global tokens (fp32) ----------------
template<int ACT, bool RES>
__global__ __launch_bounds__(128)
void small_gemm(int N, int K, int ldC,
                const float* __restrict__ A, const float* __restrict__ W,
                const float* __restrict__ bias, const float* __restrict__ R,
                float* __restrict__ C)
{
    const int r = blockIdx.y;
    const int n = blockIdx.x * 128 + threadIdx.x;
    const float* a = A + (size_t)r * K;
    float acc = 0.0f;
    #pragma unroll 8
    for (int k = 0; k < K; k++)
        acc = fmaf(__ldg(a + k), W[(size_t)k * N + n], acc);
    float v = acc + bias[n];
    if (ACT == 1) v = gelu_exact(v);
    if (RES) v += R[(size_t)r * ldC + n];
    C[(size_t)r * ldC + n] = v;
}

// ---------------- window attention: one block per (window, head) -----------
__global__ __launch_bounds__(128)
void win_attn(const __half* __restrict__ kvq, const float* __restrict__ kvqavg,
              const float* __restrict__ table,
              const float* __restrict__ xin, float* __restrict__ x1)
{
    const int w = blockIdx.x;            // 0..1023
    const int h = blockIdx.y;            // 0..15
    const int b  = w >> 6;
    const int wi = w & 63;
    const int wr = wi >> 3, wc = wi & 7;

    __shared__ float qs[36][33];
    __shared__ float ks[37][33];
    __shared__ float vs[37][33];
    __shared__ float sc[36][37];

    const int tid = threadIdx.x;

    for (int idx = tid; idx < 36 * 32; idx += 128) {
        const int m = idx >> 5, d = idx & 31;
        const int r = m / 6, c = m % 6;
        const int l = (wr * 6 + r) * 48 + wc * 6 + c;
        const __half* row = kvq + (size_t)(b * Lc + l) * NKVQ + h * 32 + d;
        ks[m][d] = __half2float(row[0]);
        vs[m][d] = __half2float(row[DIMc]);
        qs[m][d] = __half2float(row[2 * DIMc]) * SCALEc;
    }
    if (tid < 32) {
        const float* row = kvqavg + (size_t)b * NKVQ + h * 32 + tid;
        ks[36][tid] = row[0];
        vs[36][tid] = row[DIMc];
    }
    __syncthreads();

    for (int p = tid; p < 36 * 37; p += 128) {
        const int mq = p / 37, mk = p % 37;
        float acc = 0.0f;
        #pragma unroll
        for (int d = 0; d < 32; d++) acc = fmaf(qs[mq][d], ks[mk][d], acc);
        int d0, d1;
        if (mk == 36) { d0 = mq % 6; d1 = mq / 6; }
        else          { d0 = mq % 6 - mk % 6; d1 = mq / 6 - mk / 6; }
        const int idx = (d0 + 5) * 11 + (d1 + 5);
        sc[mq][mk] = acc + table[idx * NHc + h];
    }
    __syncthreads();

    if (tid < 36) {
        float mx = -1e30f;
        #pragma unroll
        for (int k = 0; k < 37; k++) mx = fmaxf(mx, sc[tid][k]);
        float sum = 0.0f;
        #pragma unroll
        for (int k = 0; k < 37; k++) { const float e = expf(sc[tid][k] - mx); sc[tid][k] = e; sum += e; }
        const float inv = 1.0f / sum;
        #pragma unroll
        for (int k = 0; k < 37; k++) sc[tid][k] *= inv;
    }
    __syncthreads();

    for (int idx = tid; idx < 36 * 32; idx += 128) {
        const int m = idx >> 5, d = idx & 31;
        float acc = 0.0f;
        #pragma unroll
        for (int k = 0; k < 37; k++) acc = fmaf(sc[m][k], vs[k][d], acc);
        const int r = m / 6, c = m % 6;
        const int l = (wr * 6 + r) * 48 + wc * 6 + c;
        const size_t o = (size_t)(b * Lc + l) * DIMc + h * 32 + d;
        x1[o] = xin[o] + acc;
    }
}

// ---------------- global-token attention: one block per (b, h) -------------
__global__ __launch_bounds__(256)
void glob_attn(const float* __restrict__ kvqavg, const __half* __restrict__ kvq,
               const float* __restrict__ xavg_in, float* __restrict__ xavg1)
{
    const int b = blockIdx.x, h = blockIdx.y;
    __shared__ float qsh[32];
    __shared__ float wgt[Lc];
    __shared__ float red[8];
    const int tid = threadIdx.x, lane = tid & 31, wn = tid >> 5;

    if (tid < 32) qsh[tid] = kvqavg[(size_t)b * NKVQ + 2 * DIMc + h * 32 + tid] * SCALEc;
    __syncthreads();

    float lmax = -1e30f;
    for (int k = tid; k < Lc; k += 256) {
        const __half2* kp = (const __half2*)(kvq + (size_t)(b * Lc + k) * NKVQ + h * 32);
        float acc = 0.0f;
        #pragma unroll
        for (int d2 = 0; d2 < 16; d2++) {
            const float2 kk = __half22float2(kp[d2]);
            acc = fmaf(qsh[d2*2+0], kk.x, acc);
            acc = fmaf(qsh[d2*2+1], kk.y, acc);
        }
        wgt[k] = acc;
        lmax = fmaxf(lmax, acc);
    }
    #pragma unroll
    for (int o = 16; o; o >>= 1) lmax = fmaxf(lmax, __shfl_xor_sync(0xffffffffu, lmax, o));
    if (lane == 0) red[wn] = lmax;
    __syncthreads();
    float gmax = red[0];
    #pragma unroll
    for (int i = 1; i < 8; i++) gmax = fmaxf(gmax, red[i]);
    __syncthreads();

    float lsum = 0.0f;
    for (int k = tid; k < Lc; k += 256) {
        const float e = expf(wgt[k] - gmax);
        wgt[k] = e;
        lsum += e;
    }
    #pragma unroll
    for (int o = 16; o; o >>= 1) lsum += __shfl_xor_sync(0xffffffffu, lsum, o);
    if (lane == 0) red[wn] = lsum;
    __syncthreads();
    float gsum = 0.0f;
    #pragma unroll
    for (int i = 0; i < 8; i++) gsum += red[i];
    const float inv = 1.0f / gsum;

    float acc[4] = {0.f, 0.f, 0.f, 0.f};
    for (int k = lane; k < Lc; k += 32) {
        const float wk = wgt[k];
        const __half2* vv = (const __half2*)(kvq + (size_t)(b * Lc + k) * NKVQ + DIMc + h * 32 + wn * 4);
        const float2 v0 = __half22float2(vv[0]);
        const float2 v1 = __half22float2(vv[1]);
        acc[0] = fmaf(wk, v0.x, acc[0]);
        acc[1] = fmaf(wk, v0.y, acc[1]);
        acc[2] = fmaf(wk, v1.x, acc[2]);
        acc[3] = fmaf(wk, v1.y, acc[3]);
    }
    #pragma unroll
    for (int j = 0; j < 4; j++) {
        #pragma unroll
        for (int o = 16; o; o >>= 1) acc[j] += __shfl_xor_sync(0xffffffffu, acc[j], o);
    }
    if (lane == 0) {
        #pragma unroll
        for (int j = 0; j < 4; j++) {
            const size_t o = (size_t)b * DIMc + h * 32 + wn * 4 + j;
            xavg1[o] = xavg_in[o] + acc[j] * inv;
        }
    }
}

// ---------------------------------------------------------------------------
extern "C" void kernel_launch(void* const* d_in, const int* in_sizes, int n_in,
                              void* d_out, int out_size)
{
    const float* x     = (const float*)d_in[0];
    const float* xavg  = (const float*)d_in[1];
    const float* w_kv  = (const float*)d_in[2];
    const float* b_kv  = (const float*)d_in[3];
    const float* w_q   = (const float*)d_in[4];
    const float* b_q   = (const float*)d_in[5];
    const float* table = (const float*)d_in[6];
    const float* g1    = (const float*)d_in[7];
    const float* be1   = (const float*)d_in[8];
    const float* g2    = (const float*)d_in[9];
    const float* be2   = (const float*)d_in[10];
    const float* w_fc1 = (const float*)d_in[11];
    const float* b_fc1 = (const float*)d_in[12];
    const float* w_fc2 = (const float*)d_in[13];
    const float* b_fc2 = (const float*)d_in[14];
    float* out = (float*)d_out;

    __half *xnh, *kvqh, *hbuf, *wkvqT, *wfc1T, *wfc2T;
    float *x1, *kvqavg, *xavgn, *xavg1, *havg, *bkvq;
    cudaGetSymbolAddress((void**)&xnh,    g_xnh);
    cudaGetSymbolAddress((void**)&kvqh,   g_kvqh);
    cudaGetSymbolAddress((void**)&x1,     g_x1);
    cudaGetSymbolAddress((void**)&hbuf,   g_h);
    cudaGetSymbolAddress((void**)&kvqavg, g_kvqavg);
    cudaGetSymbolAddress((void**)&xavgn,  g_xavgn);
    cudaGetSymbolAddress((void**)&xavg1,  g_xavg1);
    cudaGetSymbolAddress((void**)&havg,   g_havg);
    cudaGetSymbolAddress((void**)&wkvqT,  g_wkvqT);
    cudaGetSymbolAddress((void**)&bkvq,   g_bkvq);
    cudaGetSymbolAddress((void**)&wfc1T,  g_wfc1T);
    cudaGetSymbolAddress((void**)&wfc2T,  g_wfc2T);

    // 0. weight prep: transpose to [N,K] + fp16; fuse kv|q bias
    transpose_half<<<dim3(1024/32, 512/32),  dim3(32, 8)>>>(w_kv,  wkvqT,              512, 1024);
    transpose_half<<<dim3( 512/32, 512/32),  dim3(32, 8)>>>(w_q,   wkvqT + 1024 * 512, 512,  512);
    transpose_half<<<dim3(2048/32, 512/32),  dim3(32, 8)>>>(w_fc1, wfc1T,              512, 2048);
    transpose_half<<<dim3( 512/32, 2048/32), dim3(32, 8)>>>(w_fc2, wfc2T,             2048,  512);
    fuse_bias<<<6, 256>>>(b_kv, b_q, bkvq);

    // 1. LayerNorm 1
    ln_kernel_h<<<NTOK, 128>>>(x,    g1, be1, xnh);
    ln_kernel_f<<<Bc,   128>>>(xavg, g1, be1, xavgn);

    // 2. Fused kvq projection (fp16 tensor cores, half output)
    hgemm<0, false, true><<<dim3(NKVQ/128, NTOK/128), 256>>>(NTOK, NKVQ, DIMc, xnh, wkvqT, bkvq, nullptr, kvqh);
    small_gemm<0, false><<<dim3(1024/128, Bc), 128>>>(1024, DIMc, NKVQ, xavgn, w_kv, b_kv, nullptr, kvqavg);
    small_gemm<0, false><<<dim3( 512/128, Bc), 128>>>( 512, DIMc, NKVQ, xavgn, w_q,  b_q,  nullptr, kvqavg + 2 * DIMc);

    // 3. Attention (+ residual)
    win_attn <<<dim3(Bc*NWc, NHc), 128>>>(kvqh, kvqavg, table, x, x1);
    glob_attn<<<dim3(Bc,     NHc), 256>>>(kvqavg, kvqh, xavg, xavg1);

    // 4. LayerNorm 2
    ln_kernel_h<<<NTOK, 128>>>(x1,    g2, be2, xnh);
    ln_kernel_f<<<Bc,   128>>>(xavg1, g2, be2, xavgn);

    // 5. MLP (+ residual), final outputs
    hgemm<1, false, true ><<<dim3(HID/128,  NTOK/128), 256>>>(NTOK, HID,  DIMc, xnh,  wfc1T, b_fc1, nullptr, hbuf);
    hgemm<0, true,  false><<<dim3(DIMc/128, NTOK/128), 256>>>(NTOK, DIMc, HID,  hbuf, wfc2T, b_fc2, x1, out);
    small_gemm<1, false><<<dim3(HID/128,  Bc), 128>>>(HID,  DIMc, HID,  xavgn, w_fc1, b_fc1, nullptr, havg);
    small_gemm<0, true ><<<dim3(DIMc/128, Bc), 128>>>(DIMc, HID,  DIMc, havg,  w_fc2, b_fc2, xavg1, out + (size_t)NTOK * DIMc);
}